// round 1
// baseline (speedup 1.0000x reference)
#include <cuda_runtime.h>
#include <math.h>

#define BATCH 128
#define SEQ   4096
#define SD    5
#define HID   32
#define DIN   9
#define NTOK  (BATCH*SEQ)

// scratch for the cumsum'd temperature sequence (static device global: allowed)
__device__ float g_temp[NTOK];

// Accurate-enough fast tanh: (1 - e^{-2|x|}) / (1 + e^{-2|x|}) with sign copy.
// Saturates cleanly to +-1 for large |x| (layer-0 preacts reach +-200 here).
__device__ __forceinline__ float fast_tanh(float x) {
    float ax = fabsf(x);
    float e  = __expf(-2.0f * ax);
    float r  = __fdividef(1.0f - e, 1.0f + e);
    return copysignf(r, x);
}

// -------------------------------------------------------------------------
// Kernel 1: per-batch-row inclusive cumsum of delta_x[..., 2] plus init temp
// (delta_x[b, 0, 5]). One block per batch row, 1024 threads x 4 elems.
// -------------------------------------------------------------------------
__global__ __launch_bounds__(1024) void cumsum_kernel(const float* __restrict__ dx) {
    __shared__ float ssum[1024];
    const int b   = blockIdx.x;
    const int tid = threadIdx.x;
    const float* row = dx + (size_t)b * SEQ * 6;

    const int s0 = tid * 4;
    float v0 = row[(s0 + 0) * 6 + 2];
    float v1 = row[(s0 + 1) * 6 + 2];
    float v2 = row[(s0 + 2) * 6 + 2];
    float v3 = row[(s0 + 3) * 6 + 2];
    float tot = (v0 + v1) + (v2 + v3);

    ssum[tid] = tot;
    __syncthreads();

    // Hillis-Steele inclusive scan over the 1024 per-thread totals
    float acc = tot;
    #pragma unroll
    for (int off = 1; off < 1024; off <<= 1) {
        float add = (tid >= off) ? ssum[tid - off] : 0.0f;
        __syncthreads();
        acc += add;
        ssum[tid] = acc;
        __syncthreads();
    }

    float init = row[5];              // delta_x[b, 0, 5]
    float base = init + (acc - tot);  // exclusive prefix + init
    float r0 = base + v0;
    float r1 = r0 + v1;
    float r2 = r1 + v2;
    float r3 = r2 + v3;

    float* out = g_temp + (size_t)b * SEQ + s0;
    out[0] = r0; out[1] = r1; out[2] = r2; out[3] = r3;
}

// -------------------------------------------------------------------------
// Kernel 2: per-token MLP. One thread per token; weights staged in smem.
// -------------------------------------------------------------------------
__global__ __launch_bounds__(256) void msc_main(
    const float* __restrict__ h_prev,  const float* __restrict__ delta_x,
    const float* __restrict__ Wa0,     const float* __restrict__ ba0,
    const float* __restrict__ Wb0,     const float* __restrict__ bb0,
    const float* __restrict__ Wa1,     const float* __restrict__ ba1,
    const float* __restrict__ Wb1,     const float* __restrict__ bb1,
    const float* __restrict__ W_alpha, const float* __restrict__ b_alpha,
    const float* __restrict__ W_beta,  const float* __restrict__ b_beta,
    const float* __restrict__ W_gamma, const float* __restrict__ b_gamma,
    const float* __restrict__ W_c,     const float* __restrict__ b_c,
    const float* __restrict__ W_out,
    float* __restrict__ out)
{
    __shared__ float sWa0[DIN * HID], sWb0[DIN * HID];
    __shared__ float sWa1[HID * HID], sWb1[HID * HID];
    __shared__ float sWal[HID], sWbe[HID], sWga[HID], sWc[HID * SD];
    __shared__ float sba0[HID], sbb0[HID], sba1[HID], sbb1[HID];
    __shared__ float sbc[SD], sWout[SD];
    __shared__ float sbal, sbbe, sbga;

    const int tid = threadIdx.x;
    for (int i = tid; i < DIN * HID; i += 256) { sWa0[i] = Wa0[i]; sWb0[i] = Wb0[i]; }
    for (int i = tid; i < HID * HID; i += 256) { sWa1[i] = Wa1[i]; sWb1[i] = Wb1[i]; }
    for (int i = tid; i < HID; i += 256) {
        sWal[i] = W_alpha[i]; sWbe[i] = W_beta[i]; sWga[i] = W_gamma[i];
        sba0[i] = ba0[i]; sbb0[i] = bb0[i]; sba1[i] = ba1[i]; sbb1[i] = bb1[i];
    }
    for (int i = tid; i < HID * SD; i += 256) sWc[i] = W_c[i];
    if (tid < SD) { sbc[tid] = b_c[tid]; sWout[tid] = W_out[tid]; }
    if (tid == 0) { sbal = b_alpha[0]; sbbe = b_beta[0]; sbga = b_gamma[0]; }
    __syncthreads();

    const int t = blockIdx.x * 256 + tid;   // grid sized exactly to NTOK

    const float* hp = h_prev  + (size_t)t * SD;
    const float* dx = delta_x + (size_t)t * 6;

    float h[SD];
    #pragma unroll
    for (int k = 0; k < SD; k++) h[k] = hp[k];

    const float df0 = dx[0], df1 = dx[1], df2 = dx[2];
    const float temp = g_temp[t];

    float nrm = sqrtf(fmaf(df0, df0, fmaf(df1, df1, df2 * df2)));
    nrm = fmaxf(nrm, 1e-7f);
    const float inv = __fdividef(1.0f, nrm);

    float l[DIN];
    l[0] = h[0]; l[1] = h[1]; l[2] = h[2]; l[3] = h[3]; l[4] = h[4];
    l[5] = temp;
    l[6] = df0 * inv; l[7] = df1 * inv; l[8] = df2 * inv;

    // layer 0: 9 -> 32, gated tanh*tanh
    float u[HID];
    #pragma unroll
    for (int j = 0; j < HID; j++) {
        float a  = sba0[j];
        float b2 = sbb0[j];
        #pragma unroll
        for (int i = 0; i < DIN; i++) {
            a  = fmaf(l[i], sWa0[i * HID + j], a);
            b2 = fmaf(l[i], sWb0[i * HID + j], b2);
        }
        u[j] = fast_tanh(a) * fast_tanh(b2);
    }

    // layer 1: 32 -> 32, gated tanh*tanh
    float v[HID];
    #pragma unroll
    for (int j = 0; j < HID; j++) {
        float a  = sba1[j];
        float b2 = sbb1[j];
        #pragma unroll
        for (int i = 0; i < HID; i++) {
            a  = fmaf(u[i], sWa1[i * HID + j], a);
            b2 = fmaf(u[i], sWb1[i * HID + j], b2);
        }
        v[j] = fast_tanh(a) * fast_tanh(b2);
    }

    // heads
    float sa = sbal, sb = sbbe, sg = sbga;
    float c[SD];
    #pragma unroll
    for (int k = 0; k < SD; k++) c[k] = sbc[k];

    #pragma unroll
    for (int j = 0; j < HID; j++) {
        const float vj = v[j];
        sa = fmaf(vj, sWal[j], sa);
        sb = fmaf(vj, sWbe[j], sb);
        sg = fmaf(vj, sWga[j], sg);
        #pragma unroll
        for (int k = 0; k < SD; k++) c[k] = fmaf(vj, sWc[j * SD + k], c[k]);
    }

    const float alpha = __expf(sa);
    const float beta  = __expf(sb);
    const float gamma = __expf(sg);

    const float zarg = fmaf(alpha, fabsf(df0), fmaf(beta, df1, gamma * fabsf(df2)));
    const float z = 1.0f - __expf(-zarg);

    float sigma = 0.0f;
    #pragma unroll
    for (int k = 0; k < SD; k++) {
        const float cn = fast_tanh(c[k]);
        const float hn = fmaf(z, cn - h[k], h[k]);   // (1-z)h + z c
        out[(size_t)t * SD + k] = hn;
        sigma = fmaf(hn, sWout[k], sigma);
    }
    out[(size_t)NTOK * SD + t] = sigma;
}

extern "C" void kernel_launch(void* const* d_in, const int* in_sizes, int n_in,
                              void* d_out, int out_size) {
    const float* h_prev  = (const float*)d_in[0];
    const float* delta_x = (const float*)d_in[1];
    const float* Wa0     = (const float*)d_in[2];
    const float* ba0     = (const float*)d_in[3];
    const float* Wb0     = (const float*)d_in[4];
    const float* bb0     = (const float*)d_in[5];
    const float* Wa1     = (const float*)d_in[6];
    const float* ba1     = (const float*)d_in[7];
    const float* Wb1     = (const float*)d_in[8];
    const float* bb1     = (const float*)d_in[9];
    const float* W_alpha = (const float*)d_in[10];
    const float* b_alpha = (const float*)d_in[11];
    const float* W_beta  = (const float*)d_in[12];
    const float* b_beta  = (const float*)d_in[13];
    const float* W_gamma = (const float*)d_in[14];
    const float* b_gamma = (const float*)d_in[15];
    const float* W_c     = (const float*)d_in[16];
    const float* b_c     = (const float*)d_in[17];
    const float* W_out   = (const float*)d_in[18];
    float* out = (float*)d_out;

    cumsum_kernel<<<BATCH, 1024>>>(delta_x);
    msc_main<<<NTOK / 256, 256>>>(h_prev, delta_x,
                                  Wa0, ba0, Wb0, bb0,
                                  Wa1, ba1, Wb1, bb1,
                                  W_alpha, b_alpha, W_beta, b_beta,
                                  W_gamma, b_gamma, W_c, b_c, W_out,
                                  out);
}